// round 2
// baseline (speedup 1.0000x reference)
#include <cuda_runtime.h>

#define NB   256   // threads per block == rows per block
#define NBLK 256   // 256*256 = 65536 rows exactly
#define ALPHA 0.01f

// ---- shared memory layout (float offsets, all 16B-aligned) ----
#define S_WIN   0        // 3 * 8*64 = 1536
#define S_BIN   1536     // 3 * 64   = 192
#define S_WA1   1728     // 64
#define S_WA2   1792     // 64
#define S_WO1   1856     // 10*32 = 320
#define S_BO1   2176     // 32
#define S_WO2   2208     // 32*16 = 512
#define S_BO2   2720     // 16
#define S_WO3   2736     // 16
#define S_BO3   2752     // 1 (+3 pad)
#define S_WFC1  2756     // 90*64 = 5760
#define S_BFC1  8516     // 64
#define S_WIH   8580     // 192*64 = 12288
#define S_BIH   20868    // 192
#define S_WHH   21060    // 192*64 = 12288
#define S_BHH   33348    // 192
#define S_WFC2  33540    // 64*5 = 320
#define S_BFC2  33860    // 5 (+3 pad)
#define S_OBS   33868    // 256*85 = 21760 (later reused as per-row scratch, stride 65)
#define S_TOT   (33868 + 21760)   // 55628 floats = 222512 bytes

__device__ __forceinline__ float lrelu(float v) { return fmaxf(v, ALPHA * v); }
__device__ __forceinline__ float fsig(float v)  { return __fdividef(1.0f, 1.0f + __expf(-v)); }
__device__ __forceinline__ float ftanh(float v) { return 1.0f - __fdividef(2.0f, __expf(2.0f * v) + 1.0f); }

__global__ void __launch_bounds__(NB, 1)
atom_rnn_kernel(const float* __restrict__ g_obs, const float* __restrict__ g_hid,
                const float* __restrict__ w_in0, const float* __restrict__ b_in0,
                const float* __restrict__ w_in1, const float* __restrict__ b_in1,
                const float* __restrict__ w_in2, const float* __restrict__ b_in2,
                const float* __restrict__ g_W,  const float* __restrict__ g_a,
                const float* __restrict__ w_o1, const float* __restrict__ b_o1,
                const float* __restrict__ w_o2, const float* __restrict__ b_o2,
                const float* __restrict__ w_o3, const float* __restrict__ b_o3,
                const float* __restrict__ w_fc1, const float* __restrict__ b_fc1,
                const float* __restrict__ w_ih, const float* __restrict__ w_hh,
                const float* __restrict__ b_ih, const float* __restrict__ b_hh,
                const float* __restrict__ w_fc2, const float* __restrict__ b_fc2,
                float* __restrict__ out_q, float* __restrict__ out_h)
{
    extern __shared__ float sm[];
    const int tid = threadIdx.x;

    // ---------------- stage weights into shared (vectorized) ----------------
    #define CPY4(off, src, n) { const float4* s4_ = (const float4*)(src); \
                                float4* d4_ = (float4*)&sm[off]; \
                                for (int i = tid; i < (n)/4; i += NB) d4_[i] = s4_[i]; }
    CPY4(S_WIN,        w_in0, 512);
    CPY4(S_WIN + 512,  w_in1, 512);
    CPY4(S_WIN + 1024, w_in2, 512);
    CPY4(S_BIN,        b_in0, 64);
    CPY4(S_BIN + 64,   b_in1, 64);
    CPY4(S_BIN + 128,  b_in2, 64);
    CPY4(S_WO1, w_o1, 320);  CPY4(S_BO1, b_o1, 32);
    CPY4(S_WO2, w_o2, 512);  CPY4(S_BO2, b_o2, 16);
    CPY4(S_WO3, w_o3, 16);
    CPY4(S_WFC1, w_fc1, 5760); CPY4(S_BFC1, b_fc1, 64);
    CPY4(S_WIH, w_ih, 12288);  CPY4(S_BIH, b_ih, 192);
    CPY4(S_WHH, w_hh, 12288);  CPY4(S_BHH, b_hh, 192);
    CPY4(S_WFC2, w_fc2, 320);
    #undef CPY4
    if (tid == 0) sm[S_BO3] = b_o3[0];
    if (tid < 5)  sm[S_BFC2 + tid] = b_fc2[tid];

    // Wa1 = W @ a[:64], Wa2 = W @ a[64:]  (folds the 64x64 GEMM out of the hot path)
    if (tid < 128) {
        const int j = tid & 63;
        const float* av = g_a + ((tid < 64) ? 0 : 64);
        const float* wr = g_W + j * 64;
        float s = 0.f;
        #pragma unroll 8
        for (int m = 0; m < 64; ++m) s = fmaf(wr[m], av[m], s);
        sm[((tid < 64) ? S_WA1 : S_WA2) + j] = s;
    }

    // stage this block's obs tile (coalesced, vectorized)
    {
        const float4* src4 = (const float4*)(g_obs + (size_t)blockIdx.x * NB * 85);
        float4* dst4 = (float4*)&sm[S_OBS];
        for (int i = tid; i < NB * 85 / 4; i += NB) dst4[i] = src4[i];
    }
    __syncthreads();

    const int row = blockIdx.x * NB + tid;
    const float* orow = &sm[S_OBS + tid * 85];   // stride 85: conflict-free

    // ---------------- stage 1: tokens -> wh1/wh2 ----------------
    float wh1[10], wh2[10];
    #pragma unroll
    for (int t = 0; t < 10; ++t) {
        float o[8];
        #pragma unroll
        for (int f = 0; f < 8; ++f) o[f] = orow[(t * 8 + f + 4) % 80];
        const int sel = (t < 5) ? 0 : ((t < 9) ? 1 : 2);
        const float4* w4   = (const float4*)&sm[S_WIN + sel * 512];
        const float4* b4   = (const float4*)&sm[S_BIN + sel * 64];
        const float4* wa14 = (const float4*)&sm[S_WA1];
        const float4* wa24 = (const float4*)&sm[S_WA2];
        float s1 = 0.f, s2 = 0.f;
        #pragma unroll 4
        for (int jv = 0; jv < 16; ++jv) {
            float4 acc = b4[jv];
            #pragma unroll
            for (int f = 0; f < 8; ++f) {
                float4 wv = w4[f * 16 + jv];
                acc.x = fmaf(o[f], wv.x, acc.x);
                acc.y = fmaf(o[f], wv.y, acc.y);
                acc.z = fmaf(o[f], wv.z, acc.z);
                acc.w = fmaf(o[f], wv.w, acc.w);
            }
            acc.x = lrelu(acc.x); acc.y = lrelu(acc.y);
            acc.z = lrelu(acc.z); acc.w = lrelu(acc.w);
            float4 a1 = wa14[jv], a2 = wa24[jv];
            s1 = fmaf(acc.x, a1.x, s1); s1 = fmaf(acc.y, a1.y, s1);
            s1 = fmaf(acc.z, a1.z, s1); s1 = fmaf(acc.w, a1.w, s1);
            s2 = fmaf(acc.x, a2.x, s2); s2 = fmaf(acc.y, a2.y, s2);
            s2 = fmaf(acc.z, a2.z, s2); s2 = fmaf(acc.w, a2.w, s2);
        }
        wh1[t] = s1; wh2[t] = s2;
    }

    // ---------------- stage 2: attention + output head ----------------
    // Precompute att1 softmax stats per column c (static indices)
    float mx1[5], dinv1[5];
    #pragma unroll
    for (int c = 0; c < 5; ++c) {
        float mx = -1e30f;
        #pragma unroll
        for (int r2 = 0; r2 < 5; ++r2) mx = fmaxf(mx, lrelu(wh1[5 + c] + wh2[r2]));
        float d = 0.f;
        #pragma unroll
        for (int r2 = 0; r2 < 5; ++r2) d += __expf(lrelu(wh1[5 + c] + wh2[r2]) - mx);
        mx1[c] = mx; dinv1[c] = __fdividef(1.0f, d);
    }

    float hpv0, hpv1, hpv2, hpv3, hpv4;
    #pragma unroll 1
    for (int r = 0; r < 5; ++r) {
        const float w1r = (r == 0) ? wh1[0] : (r == 1) ? wh1[1] : (r == 2) ? wh1[2] : (r == 3) ? wh1[3] : wh1[4];
        const float w2r = (r == 0) ? wh2[0] : (r == 1) ? wh2[1] : (r == 2) ? wh2[2] : (r == 3) ? wh2[3] : wh2[4];
        float att[10];
        {
            float ev[5]; float mx = -1e30f;
            #pragma unroll
            for (int c = 0; c < 5; ++c) {
                float v = lrelu(w1r + wh2[5 + c]);
                ev[c] = v; mx = fmaxf(mx, v);
            }
            float d = 0.f;
            #pragma unroll
            for (int c = 0; c < 5; ++c) { float e_ = __expf(ev[c] - mx); att[c] = e_; d += e_; }
            float inv = __fdividef(1.0f, d);
            #pragma unroll
            for (int c = 0; c < 5; ++c) att[c] *= inv;
            #pragma unroll
            for (int c = 0; c < 5; ++c)
                att[5 + c] = __expf(lrelu(wh1[5 + c] + w2r) - mx1[c]) * dinv1[c];
        }
        // h1 = lrelu(att @ w_o1 + b_o1), vectorized over j
        float h1[32];
        {
            const float4* wv4 = (const float4*)&sm[S_WO1];
            const float4* bv4 = (const float4*)&sm[S_BO1];
            #pragma unroll
            for (int jv = 0; jv < 8; ++jv) {
                float4 acc = bv4[jv];
                #pragma unroll
                for (int k = 0; k < 10; ++k) {
                    float4 wv = wv4[k * 8 + jv];
                    acc.x = fmaf(att[k], wv.x, acc.x);
                    acc.y = fmaf(att[k], wv.y, acc.y);
                    acc.z = fmaf(att[k], wv.z, acc.z);
                    acc.w = fmaf(att[k], wv.w, acc.w);
                }
                h1[4*jv]   = lrelu(acc.x); h1[4*jv+1] = lrelu(acc.y);
                h1[4*jv+2] = lrelu(acc.z); h1[4*jv+3] = lrelu(acc.w);
            }
        }
        float h2v[16];
        {
            const float4* wv4 = (const float4*)&sm[S_WO2];
            const float4* bv4 = (const float4*)&sm[S_BO2];
            #pragma unroll
            for (int jv = 0; jv < 4; ++jv) {
                float4 acc = bv4[jv];
                #pragma unroll
                for (int k = 0; k < 32; ++k) {
                    float4 wv = wv4[k * 4 + jv];
                    acc.x = fmaf(h1[k], wv.x, acc.x);
                    acc.y = fmaf(h1[k], wv.y, acc.y);
                    acc.z = fmaf(h1[k], wv.z, acc.z);
                    acc.w = fmaf(h1[k], wv.w, acc.w);
                }
                h2v[4*jv]   = lrelu(acc.x); h2v[4*jv+1] = lrelu(acc.y);
                h2v[4*jv+2] = lrelu(acc.z); h2v[4*jv+3] = lrelu(acc.w);
            }
        }
        float v = sm[S_BO3];
        {
            const float4* wv4 = (const float4*)&sm[S_WO3];
            #pragma unroll
            for (int kv = 0; kv < 4; ++kv) {
                float4 wv = wv4[kv];
                v = fmaf(h2v[4*kv],   wv.x, v);
                v = fmaf(h2v[4*kv+1], wv.y, v);
                v = fmaf(h2v[4*kv+2], wv.z, v);
                v = fmaf(h2v[4*kv+3], wv.w, v);
            }
        }
        v = lrelu(v);
        hpv0 = (r == 0) ? v : hpv0;
        hpv1 = (r == 1) ? v : hpv1;
        hpv2 = (r == 2) ? v : hpv2;
        hpv3 = (r == 3) ? v : hpv3;
        hpv4 = (r == 4) ? v : hpv4;
    }

    float obs_out[5];
    {
        float mx = fmaxf(fmaxf(fmaxf(hpv0, hpv1), fmaxf(hpv2, hpv3)), hpv4);
        obs_out[0] = __expf(hpv0 - mx); obs_out[1] = __expf(hpv1 - mx);
        obs_out[2] = __expf(hpv2 - mx); obs_out[3] = __expf(hpv3 - mx);
        obs_out[4] = __expf(hpv4 - mx);
        float d = obs_out[0] + obs_out[1] + obs_out[2] + obs_out[3] + obs_out[4];
        float inv = __fdividef(1.0f, d);
        #pragma unroll
        for (int r = 0; r < 5; ++r) obs_out[r] *= inv;
    }

    // ---------------- stage 3: fc1 (vectorized weight loads) ----------------
    float x[64];
    {
        const float4* bv4 = (const float4*)&sm[S_BFC1];
        #pragma unroll
        for (int jv = 0; jv < 16; ++jv) {
            float4 b = bv4[jv];
            x[4*jv] = b.x; x[4*jv+1] = b.y; x[4*jv+2] = b.z; x[4*jv+3] = b.w;
        }
    }
    #pragma unroll 2
    for (int k = 0; k < 85; ++k) {
        const float ok = orow[k];
        const float4* wr4 = (const float4*)&sm[S_WFC1 + k * 64];
        #pragma unroll
        for (int jv = 0; jv < 16; ++jv) {
            float4 wv = wr4[jv];
            x[4*jv]   = fmaf(ok, wv.x, x[4*jv]);
            x[4*jv+1] = fmaf(ok, wv.y, x[4*jv+1]);
            x[4*jv+2] = fmaf(ok, wv.z, x[4*jv+2]);
            x[4*jv+3] = fmaf(ok, wv.w, x[4*jv+3]);
        }
    }
    #pragma unroll
    for (int m = 0; m < 5; ++m) {
        const float om = obs_out[m];
        const float4* wr4 = (const float4*)&sm[S_WFC1 + (85 + m) * 64];
        #pragma unroll
        for (int jv = 0; jv < 16; ++jv) {
            float4 wv = wr4[jv];
            x[4*jv]   = fmaf(om, wv.x, x[4*jv]);
            x[4*jv+1] = fmaf(om, wv.y, x[4*jv+1]);
            x[4*jv+2] = fmaf(om, wv.z, x[4*jv+2]);
            x[4*jv+3] = fmaf(om, wv.w, x[4*jv+3]);
        }
    }
    #pragma unroll
    for (int j = 0; j < 64; ++j) x[j] = fmaxf(x[j], 0.f);

    // ---------------- stage 4: GRU + q ----------------
    float hi[64];
    {
        const float4* hp4 = (const float4*)(g_hid + (size_t)row * 64);
        #pragma unroll
        for (int i = 0; i < 16; ++i) {
            float4 v = hp4[i];
            hi[4*i] = v.x; hi[4*i+1] = v.y; hi[4*i+2] = v.z; hi[4*i+3] = v.w;
        }
    }
    __syncthreads();                     // obs tile dead -> reuse as per-row scratch
    float* scr = &sm[S_OBS + tid * 65];  // stride 65 -> conflict-free dynamic access
    #pragma unroll
    for (int k = 0; k < 64; ++k) scr[k] = hi[k];

    float hq[5];
    #pragma unroll
    for (int m = 0; m < 5; ++m) hq[m] = sm[S_BFC2 + m];

    #pragma unroll 1
    for (int j = 0; j < 64; ++j) {
        const float4* wiR = (const float4*)&sm[S_WIH + j * 64];
        const float4* wiZ = (const float4*)&sm[S_WIH + (64 + j) * 64];
        const float4* wiN = (const float4*)&sm[S_WIH + (128 + j) * 64];
        const float4* whR = (const float4*)&sm[S_WHH + j * 64];
        const float4* whZ = (const float4*)&sm[S_WHH + (64 + j) * 64];
        const float4* whN = (const float4*)&sm[S_WHH + (128 + j) * 64];
        float axr = sm[S_BIH + j],       ahr = sm[S_BHH + j];
        float axz = sm[S_BIH + 64 + j],  ahz = sm[S_BHH + 64 + j];
        float axn = sm[S_BIH + 128 + j], ahn = sm[S_BHH + 128 + j];
        #pragma unroll
        for (int kv = 0; kv < 16; ++kv) {
            float4 wr = wiR[kv], wz = wiZ[kv], wn = wiN[kv];
            float4 vr = whR[kv], vz = whZ[kv], vn = whN[kv];
            axr = fmaf(x[4*kv],   wr.x, axr); axr = fmaf(x[4*kv+1], wr.y, axr);
            axr = fmaf(x[4*kv+2], wr.z, axr); axr = fmaf(x[4*kv+3], wr.w, axr);
            ahr = fmaf(hi[4*kv],   vr.x, ahr); ahr = fmaf(hi[4*kv+1], vr.y, ahr);
            ahr = fmaf(hi[4*kv+2], vr.z, ahr); ahr = fmaf(hi[4*kv+3], vr.w, ahr);
            axz = fmaf(x[4*kv],   wz.x, axz); axz = fmaf(x[4*kv+1], wz.y, axz);
            axz = fmaf(x[4*kv+2], wz.z, axz); axz = fmaf(x[4*kv+3], wz.w, axz);
            ahz = fmaf(hi[4*kv],   vz.x, ahz); ahz = fmaf(hi[4*kv+1], vz.y, ahz);
            ahz = fmaf(hi[4*kv+2], vz.z, ahz); ahz = fmaf(hi[4*kv+3], vz.w, ahz);
            axn = fmaf(x[4*kv],   wn.x, axn); axn = fmaf(x[4*kv+1], wn.y, axn);
            axn = fmaf(x[4*kv+2], wn.z, axn); axn = fmaf(x[4*kv+3], wn.w, axn);
            ahn = fmaf(hi[4*kv],   vn.x, ahn); ahn = fmaf(hi[4*kv+1], vn.y, ahn);
            ahn = fmaf(hi[4*kv+2], vn.z, ahn); ahn = fmaf(hi[4*kv+3], vn.w, ahn);
        }
        const float r_ = fsig(axr + ahr);
        const float z_ = fsig(axz + ahz);
        const float n_ = ftanh(fmaf(r_, ahn, axn));
        const float hj = scr[j];                    // h_in[j]
        const float h_ = n_ + z_ * (hj - n_);       // (1-z)n + z*h_in
        scr[j] = h_;
        #pragma unroll
        for (int m = 0; m < 5; ++m) hq[m] = fmaf(h_, sm[S_WFC2 + j * 5 + m], hq[m]);
    }

    // ---------------- stores ----------------
    {
        float* qp = out_q + (size_t)row * 5;
        #pragma unroll
        for (int m = 0; m < 5; ++m) qp[m] = hq[m];

        float4* ho4 = (float4*)(out_h + (size_t)row * 64);
        #pragma unroll 1
        for (int i = 0; i < 16; ++i) {
            float4 v;
            v.x = scr[4*i]; v.y = scr[4*i+1]; v.z = scr[4*i+2]; v.w = scr[4*i+3];
            ho4[i] = v;
        }
    }
}

extern "C" void kernel_launch(void* const* d_in, const int* in_sizes, int n_in,
                              void* d_out, int out_size)
{
    const float* g_obs  = (const float*)d_in[0];
    const float* g_hid  = (const float*)d_in[1];
    const float* w_in0  = (const float*)d_in[2];
    const float* b_in0  = (const float*)d_in[3];
    const float* w_in1  = (const float*)d_in[4];
    const float* b_in1  = (const float*)d_in[5];
    const float* w_in2  = (const float*)d_in[6];
    const float* b_in2  = (const float*)d_in[7];
    const float* g_W    = (const float*)d_in[8];
    const float* g_a    = (const float*)d_in[9];
    const float* w_o1   = (const float*)d_in[10];
    const float* b_o1   = (const float*)d_in[11];
    const float* w_o2   = (const float*)d_in[12];
    const float* b_o2   = (const float*)d_in[13];
    const float* w_o3   = (const float*)d_in[14];
    const float* b_o3   = (const float*)d_in[15];
    const float* w_fc1  = (const float*)d_in[16];
    const float* b_fc1  = (const float*)d_in[17];
    const float* w_ih   = (const float*)d_in[18];
    const float* w_hh   = (const float*)d_in[19];
    const float* b_ih   = (const float*)d_in[20];
    const float* b_hh   = (const float*)d_in[21];
    const float* w_fc2  = (const float*)d_in[22];
    const float* b_fc2  = (const float*)d_in[23];

    float* out   = (float*)d_out;
    float* out_q = out;                          // q: (65536, 5) flattened first
    float* out_h = out + (size_t)65536 * 5;      // h: (65536, 64) after

    const int smem_bytes = S_TOT * 4;            // 222512 B
    cudaFuncSetAttribute(atom_rnn_kernel,
                         cudaFuncAttributeMaxDynamicSharedMemorySize, smem_bytes);

    atom_rnn_kernel<<<NBLK, NB, smem_bytes>>>(
        g_obs, g_hid, w_in0, b_in0, w_in1, b_in1, w_in2, b_in2, g_W, g_a,
        w_o1, b_o1, w_o2, b_o2, w_o3, b_o3, w_fc1, b_fc1,
        w_ih, w_hh, b_ih, b_hh, w_fc2, b_fc2, out_q, out_h);
}